// round 12
// baseline (speedup 1.0000x reference)
#include <cuda_runtime.h>
#include <float.h>

// _VQ_29609504538631 : fused VQ-VAE bottleneck
// R11: balanced launch done RIGHT. grid = 296 (=2x148) -> exactly 2 CTAs/SM.
// Each block owns pairs [floor(32768*bid/296), floor(32768*(bid+1)/296))
// (110-111 pairs). Inactive pair-slots skip ALL per-token phases (1, 2b,
// rescore, 3) and just park at barriers (R10 bug: they ran phases 1+2).
// Per-token math bit-identical to R9 (chunk-64 fp32 + fp64 merge e, fp64
// half-norms, paired scan + branchless top-2, fp64 rescore of 4 cands).

namespace {
constexpr int Bb = 8;
constexpr int Cc = 1024;
constexpr int Tt = 8192;
constexpr int Kk = 1024;
constexpr int Dd = 8;
constexpr int NP  = 128;              // pair slots per block (110-111 used)
constexpr int SL  = 2;                // channel/code slices per token
constexpr int NT  = NP * SL;          // 256 threads
constexpr int CH  = Cc / SL;          // 512 channels per slice
constexpr int KH  = Kk / SL;          // 512 codes per slice
constexpr int CHUNK = 64;             // fp32 accumulation chunk (validated)
constexpr int GRID  = 296;            // 2 x 148 SMs
constexpr int NPAIR = (Bb * Tt) / 2;  // 32768 total token-pairs
}

typedef unsigned long long u64;

__device__ __forceinline__ u64 pk2(float lo, float hi) {
    u64 r; asm("mov.b64 %0, {%1,%2};" : "=l"(r) : "f"(lo), "f"(hi)); return r;
}
__device__ __forceinline__ void upk2(u64 v, float& lo, float& hi) {
    asm("mov.b64 {%0,%1}, %2;" : "=f"(lo), "=f"(hi) : "l"(v));
}
__device__ __forceinline__ u64 ffma2(u64 a, u64 b, u64 c) {
    u64 r; asm("fma.rn.f32x2 %0, %1, %2, %3;" : "=l"(r) : "l"(a), "l"(b), "l"(c)); return r;
}

__global__ __launch_bounds__(NT, 2) void vq_fused(
    const float* __restrict__ z,
    const float* __restrict__ in_w,    // [D, C]
    const float* __restrict__ in_b,    // [D]
    const float* __restrict__ cb,      // [K, D]
    const float* __restrict__ out_w,   // [C, D]
    const float* __restrict__ out_b,   // [C]
    float* __restrict__ out,           // [B, C, T]
    float* __restrict__ ids_out)       // [B, T] (as float), may be null
{
    __shared__ __align__(16) float buf[Dd * Cc];    // 32 KB: in_w->cb->out_w
    __shared__ u64    aux2[Kk];                     // 8 KB: (-0.5||w||^2,0)/(out_b,0)
    __shared__ double exch[SL][NP][2][Dd];          // 32 KB fp64 partials
    __shared__ int    cand_i[SL][NP][2][2];         // 4 KB candidate ids
    __shared__ float  bias_in[Dd];

    const int tid   = threadIdx.x;
    const int slice = tid >> 7;           // 0/1
    const int pr    = tid & (NP - 1);     // pair slot in block

    // balanced pair-range for this block
    const int pstart = (int)(((long long)NPAIR * blockIdx.x) / GRID);
    const int pend   = (int)(((long long)NPAIR * (blockIdx.x + 1)) / GRID);
    const bool active = (pstart + pr) < pend;
    const int p     = min(pstart + pr, NPAIR - 1);   // clamped (addr-safe)
    const int g     = 2 * p;                          // global token index
    const int b     = g >> 13;                        // / Tt
    const int t0    = g & (Tt - 1);                   // % Tt (even)

    // ---- Phase 0: stage in_w transposed -> buf[c*8+d]  (all threads)
    for (int i = tid; i < Dd * Cc; i += NT) {
        int d = i & 7, c = i >> 3;
        buf[i] = in_w[d * Cc + c];
    }
    if (tid < Dd) bias_in[tid] = in_b[tid];
    __syncthreads();

    // ---- Phase 1: partial e over this slice's 512 channels, 2 tokens packed.
    float e0[Dd], e1[Dd];
    if (active) {
        double p0[Dd], p1[Dd];
        #pragma unroll
        for (int d = 0; d < Dd; d++) { p0[d] = 0.0; p1[d] = 0.0; }

        const float* zp = z + (size_t)b * Cc * Tt + t0;
        const int cbeg = slice * CH;
        for (int c0 = cbeg; c0 < cbeg + CH; c0 += CHUNK) {
            u64 a0[4], a1[4];
            #pragma unroll
            for (int j = 0; j < 4; j++) { a0[j] = 0ull; a1[j] = 0ull; }
            #pragma unroll 8
            for (int cc = 0; cc < CHUNK; cc++) {
                int c = c0 + cc;
                float2 v2 = __ldg(reinterpret_cast<const float2*>(zp + (size_t)c * Tt));
                u64 v0 = pk2(v2.x, v2.x);
                u64 v1 = pk2(v2.y, v2.y);
                const ulonglong2* wp = reinterpret_cast<const ulonglong2*>(buf + c * 8);
                ulonglong2 wA = wp[0];
                ulonglong2 wB = wp[1];
                a0[0] = ffma2(v0, wA.x, a0[0]);
                a0[1] = ffma2(v0, wA.y, a0[1]);
                a0[2] = ffma2(v0, wB.x, a0[2]);
                a0[3] = ffma2(v0, wB.y, a0[3]);
                a1[0] = ffma2(v1, wA.x, a1[0]);
                a1[1] = ffma2(v1, wA.y, a1[1]);
                a1[2] = ffma2(v1, wB.x, a1[2]);
                a1[3] = ffma2(v1, wB.y, a1[3]);
            }
            #pragma unroll
            for (int j = 0; j < 4; j++) {
                float lo, hi;
                upk2(a0[j], lo, hi); p0[2*j] += (double)lo; p0[2*j+1] += (double)hi;
                upk2(a1[j], lo, hi); p1[2*j] += (double)lo; p1[2*j+1] += (double)hi;
            }
        }
        #pragma unroll
        for (int d = 0; d < Dd; d++) {
            exch[slice][pr][0][d] = p0[d];
            exch[slice][pr][1][d] = p1[d];
        }
    }
    __syncthreads();   // buf(in_w) reads done; partials published

    if (active) {
        // merge partials in identical order on both slice threads
        #pragma unroll
        for (int d = 0; d < Dd; d++) {
            e0[d] = (float)((exch[0][pr][0][d] + exch[1][pr][0][d]) + (double)bias_in[d]);
            e1[d] = (float)((exch[0][pr][1][d] + exch[1][pr][1][d]) + (double)bias_in[d]);
        }
    }

    // ---- Phase 2a: stage codebook + pre-paired (-0.5||w||^2, 0)  (all threads)
    for (int k = tid; k < Kk; k += NT) {
        float4 c0 = __ldg(reinterpret_cast<const float4*>(cb + k * 8));
        float4 c1 = __ldg(reinterpret_cast<const float4*>(cb + k * 8) + 1);
        reinterpret_cast<float4*>(buf)[k * 2]     = c0;
        reinterpret_cast<float4*>(buf)[k * 2 + 1] = c1;
        double n = (double)c0.x*c0.x + (double)c0.y*c0.y
                 + (double)c0.z*c0.z + (double)c0.w*c0.w
                 + (double)c1.x*c1.x + (double)c1.y*c1.y
                 + (double)c1.z*c1.z + (double)c1.w*c1.w;
        aux2[k] = pk2(-(float)(0.5 * n), 0.0f);
    }
    __syncthreads();

    // ---- Phase 2b + rescore: only active pairs scan
    int bi0 = 0, bi1 = 0;
    if (active) {
        u64 ep0[4], ep1[4];
        #pragma unroll
        for (int j = 0; j < 4; j++) {
            ep0[j] = pk2(e0[2*j], e0[2*j+1]);
            ep1[j] = pk2(e1[2*j], e1[2*j+1]);
        }
        float b1t0 = -FLT_MAX, b2t0 = -FLT_MAX, b1t1 = -FLT_MAX, b2t1 = -FLT_MAX;
        int   i1t0 = slice*KH, i2t0 = slice*KH, i1t1 = slice*KH, i2t1 = slice*KH;
        const int kbeg = slice * KH;
        #pragma unroll 2
        for (int k = kbeg; k < kbeg + KH; k += 2) {
            const ulonglong2* wp = reinterpret_cast<const ulonglong2*>(buf + k * 8);
            ulonglong2 wa0 = wp[0], wa1 = wp[1];   // code k
            ulonglong2 wb0 = wp[2], wb1 = wp[3];   // code k+1
            ulonglong2 iab = *reinterpret_cast<const ulonglong2*>(&aux2[k]);
            u64 da = ffma2(ep0[3], wa1.y, ffma2(ep0[2], wa1.x,
                     ffma2(ep0[1], wa0.y, ffma2(ep0[0], wa0.x, iab.x))));
            u64 db = ffma2(ep0[3], wb1.y, ffma2(ep0[2], wb1.x,
                     ffma2(ep0[1], wb0.y, ffma2(ep0[0], wb0.x, iab.y))));
            float lo, hi;
            upk2(da, lo, hi); float sa0 = lo + hi;
            upk2(db, lo, hi); float sb0 = lo + hi;
            da = ffma2(ep1[3], wa1.y, ffma2(ep1[2], wa1.x,
                 ffma2(ep1[1], wa0.y, ffma2(ep1[0], wa0.x, iab.x))));
            db = ffma2(ep1[3], wb1.y, ffma2(ep1[2], wb1.x,
                 ffma2(ep1[1], wb0.y, ffma2(ep1[0], wb0.x, iab.y))));
            upk2(da, lo, hi); float sa1 = lo + hi;
            upk2(db, lo, hi); float sb1 = lo + hi;
            {
                bool pa = sa0 >= sb0;
                float sm = pa ? sa0 : sb0;
                int   km = pa ? k : k + 1;
                bool q2 = sm > b2t0;
                float c2 = q2 ? sm : b2t0;  int j2 = q2 ? km : i2t0;
                bool q1 = sm > b1t0;
                b2t0 = q1 ? b1t0 : c2;      i2t0 = q1 ? i1t0 : j2;
                b1t0 = q1 ? sm : b1t0;      i1t0 = q1 ? km : i1t0;
            }
            {
                bool pa = sa1 >= sb1;
                float sm = pa ? sa1 : sb1;
                int   km = pa ? k : k + 1;
                bool q2 = sm > b2t1;
                float c2 = q2 ? sm : b2t1;  int j2 = q2 ? km : i2t1;
                bool q1 = sm > b1t1;
                b2t1 = q1 ? b1t1 : c2;      i2t1 = q1 ? i1t1 : j2;
                b1t1 = q1 ? sm : b1t1;      i1t1 = q1 ? km : i1t1;
            }
        }
        cand_i[slice][pr][0][0] = i1t0;  cand_i[slice][pr][0][1] = i2t0;
        cand_i[slice][pr][1][0] = i1t1;  cand_i[slice][pr][1][1] = i2t1;
    }
    __syncthreads();

    u64 q0p[4], q1p[4];
    if (active) {
        // ---- fp64 rescore of all 4 candidates per token; lowest index on ties.
        #pragma unroll
        for (int tk = 0; tk < 2; tk++) {
            const float* ee = tk ? e1 : e0;
            double bscore = -DBL_MAX;
            int    bidx   = Kk;
            #pragma unroll
            for (int j = 0; j < 4; j++) {
                int kc = cand_i[j >> 1][pr][tk][j & 1];
                const float* w = buf + kc * 8;
                double dot = 0.0, nrm = 0.0;
                #pragma unroll
                for (int i = 0; i < Dd; i++) {
                    double wi = (double)w[i];
                    dot += (double)ee[i] * wi;
                    nrm += wi * wi;
                }
                double sc = dot - 0.5 * nrm;
                if (sc > bscore || (sc == bscore && kc < bidx)) {
                    bscore = sc; bidx = kc;
                }
            }
            if (tk) bi1 = bidx; else bi0 = bidx;
        }
        // grab winning codes (as d-pairs) before buf is overwritten
        const ulonglong2* w0 = reinterpret_cast<const ulonglong2*>(buf + bi0 * 8);
        const ulonglong2* w1 = reinterpret_cast<const ulonglong2*>(buf + bi1 * 8);
        ulonglong2 x0 = w0[0], x1 = w0[1], y0 = w1[0], y1 = w1[1];
        q0p[0] = x0.x; q0p[1] = x0.y; q0p[2] = x1.x; q0p[3] = x1.y;
        q1p[0] = y0.x; q1p[1] = y0.y; q1p[2] = y1.x; q1p[3] = y1.y;
    }
    __syncthreads();   // codebook reads done

    // ---- Phase 3a: stage out_w; aux2 <- (out_b, 0)  (all threads)
    for (int i = tid; i < Cc * Dd; i += NT) buf[i] = out_w[i];
    for (int i = tid; i < Cc; i += NT)      aux2[i] = pk2(out_b[i], 0.0f);
    __syncthreads();

    // ---- Phase 3b: active pairs write channels [cbeg, cbeg+512), 2 tokens.
    if (active) {
        const int cbeg = slice * CH;
        float* op = out + (size_t)b * Cc * Tt + t0;
        #pragma unroll 4
        for (int c = cbeg; c < cbeg + CH; c++) {
            const ulonglong2* wp = reinterpret_cast<const ulonglong2*>(buf + c * 8);
            ulonglong2 wA = wp[0], wB = wp[1];
            u64 ic = aux2[c];
            u64 d0 = ffma2(q0p[3], wB.y, ffma2(q0p[2], wB.x,
                     ffma2(q0p[1], wA.y, ffma2(q0p[0], wA.x, ic))));
            u64 d1 = ffma2(q1p[3], wB.y, ffma2(q1p[2], wB.x,
                     ffma2(q1p[1], wA.y, ffma2(q1p[0], wA.x, ic))));
            float lo, hi;
            upk2(d0, lo, hi); float s0 = lo + hi;
            upk2(d1, lo, hi); float s1 = lo + hi;
            *reinterpret_cast<float2*>(op + (size_t)c * Tt) = make_float2(s0, s1);
        }
        if (slice == 0 && ids_out) {
            *reinterpret_cast<float2*>(ids_out + (size_t)b * Tt + t0) =
                make_float2((float)bi0, (float)bi1);
        }
    }
}

extern "C" void kernel_launch(void* const* d_in, const int* in_sizes, int n_in,
                              void* d_out, int out_size) {
    const float* z     = (const float*)d_in[0];
    const float* in_w  = (const float*)d_in[1];
    const float* in_b  = (const float*)d_in[2];
    const float* cb    = (const float*)d_in[3];
    const float* out_w = (const float*)d_in[4];
    const float* out_b = (const float*)d_in[5];

    float* out = (float*)d_out;
    const long long out_elems = (long long)Bb * Cc * Tt;
    float* ids = (out_size > out_elems) ? out + out_elems : nullptr;

    vq_fused<<<GRID, NT>>>(z, in_w, in_b, cb, out_w, out_b, out, ids);
}

// round 13
// speedup vs baseline: 1.3267x; 1.3267x over previous
#include <cuda_runtime.h>
#include <float.h>

// _VQ_29609504538631 : fused VQ-VAE bottleneck
// R12: R9 base (grid 256x256, 2 tokens/thread, SL=2 slicing) + ILP diet:
//   - phase 2 scans codes in groups of 4: two-level max-tree (ties->lower k),
//     ONE top-2 update per token per 4 codes; w-regs reused pairwise
//   - phase 3 unroll 8, phase 1 unroll 16
// e math bit-identical to R9 (chunk-64 fp32 + fp64 merge); fp64 half-norms;
// fp64 rescore of 4 candidates per token unchanged.

namespace {
constexpr int Bb = 8;
constexpr int Cc = 1024;
constexpr int Tt = 8192;
constexpr int Kk = 1024;
constexpr int Dd = 8;
constexpr int TT  = 256;              // tokens per block (128 pairs)
constexpr int NP  = 128;              // token-pairs per block
constexpr int SL  = 2;                // channel/code slices per token
constexpr int NT  = NP * SL;          // 256 threads
constexpr int CH  = Cc / SL;          // 512 channels per slice
constexpr int KH  = Kk / SL;          // 512 codes per slice
constexpr int CHUNK = 64;             // fp32 accumulation chunk (validated)
}

typedef unsigned long long u64;

__device__ __forceinline__ u64 pk2(float lo, float hi) {
    u64 r; asm("mov.b64 %0, {%1,%2};" : "=l"(r) : "f"(lo), "f"(hi)); return r;
}
__device__ __forceinline__ void upk2(u64 v, float& lo, float& hi) {
    asm("mov.b64 {%0,%1}, %2;" : "=f"(lo), "=f"(hi) : "l"(v));
}
__device__ __forceinline__ u64 ffma2(u64 a, u64 b, u64 c) {
    u64 r; asm("fma.rn.f32x2 %0, %1, %2, %3;" : "=l"(r) : "l"(a), "l"(b), "l"(c)); return r;
}

__global__ __launch_bounds__(NT, 2) void vq_fused(
    const float* __restrict__ z,
    const float* __restrict__ in_w,    // [D, C]
    const float* __restrict__ in_b,    // [D]
    const float* __restrict__ cb,      // [K, D]
    const float* __restrict__ out_w,   // [C, D]
    const float* __restrict__ out_b,   // [C]
    float* __restrict__ out,           // [B, C, T]
    float* __restrict__ ids_out)       // [B, T] (as float), may be null
{
    __shared__ __align__(16) float buf[Dd * Cc];    // 32 KB: in_w->cb->out_w
    __shared__ __align__(16) u64 aux2[Kk];          // 8 KB: (-0.5||w||^2,0)/(out_b,0)
    __shared__ double exch[SL][NP][2][Dd];          // 32 KB fp64 partials
    __shared__ int    cand_i[SL][NP][2][2];         // 4 KB candidate ids
    __shared__ float  bias_in[Dd];

    const int tid   = threadIdx.x;
    const int slice = tid >> 7;           // 0/1
    const int pr    = tid & (NP - 1);     // pair index in block
    const int b     = blockIdx.x / (Tt / TT);
    const int t0    = (blockIdx.x % (Tt / TT)) * TT + 2 * pr;   // even

    // ---- Phase 0: stage in_w transposed -> buf[c*8+d]
    for (int i = tid; i < Dd * Cc; i += NT) {
        int d = i & 7, c = i >> 3;
        buf[i] = in_w[d * Cc + c];
    }
    if (tid < Dd) bias_in[tid] = in_b[tid];
    __syncthreads();

    // ---- Phase 1: partial e over this slice's 512 channels, 2 tokens packed.
    double p0[Dd], p1[Dd];
    #pragma unroll
    for (int d = 0; d < Dd; d++) { p0[d] = 0.0; p1[d] = 0.0; }

    const float* zp = z + (size_t)b * Cc * Tt + t0;
    const int cbeg = slice * CH;
    for (int c0 = cbeg; c0 < cbeg + CH; c0 += CHUNK) {
        u64 a0[4], a1[4];
        #pragma unroll
        for (int j = 0; j < 4; j++) { a0[j] = 0ull; a1[j] = 0ull; }
        #pragma unroll 16
        for (int cc = 0; cc < CHUNK; cc++) {
            int c = c0 + cc;
            float2 v2 = __ldg(reinterpret_cast<const float2*>(zp + (size_t)c * Tt));
            u64 v0 = pk2(v2.x, v2.x);
            u64 v1 = pk2(v2.y, v2.y);
            const ulonglong2* wp = reinterpret_cast<const ulonglong2*>(buf + c * 8);
            ulonglong2 wA = wp[0];
            ulonglong2 wB = wp[1];
            a0[0] = ffma2(v0, wA.x, a0[0]);
            a0[1] = ffma2(v0, wA.y, a0[1]);
            a0[2] = ffma2(v0, wB.x, a0[2]);
            a0[3] = ffma2(v0, wB.y, a0[3]);
            a1[0] = ffma2(v1, wA.x, a1[0]);
            a1[1] = ffma2(v1, wA.y, a1[1]);
            a1[2] = ffma2(v1, wB.x, a1[2]);
            a1[3] = ffma2(v1, wB.y, a1[3]);
        }
        #pragma unroll
        for (int j = 0; j < 4; j++) {
            float lo, hi;
            upk2(a0[j], lo, hi); p0[2*j] += (double)lo; p0[2*j+1] += (double)hi;
            upk2(a1[j], lo, hi); p1[2*j] += (double)lo; p1[2*j+1] += (double)hi;
        }
    }
    #pragma unroll
    for (int d = 0; d < Dd; d++) {
        exch[slice][pr][0][d] = p0[d];
        exch[slice][pr][1][d] = p1[d];
    }
    __syncthreads();   // buf(in_w) reads done; partials published

    // merge partials in identical order on both slice threads
    float e0[Dd], e1[Dd];
    #pragma unroll
    for (int d = 0; d < Dd; d++) {
        e0[d] = (float)((exch[0][pr][0][d] + exch[1][pr][0][d]) + (double)bias_in[d]);
        e1[d] = (float)((exch[0][pr][1][d] + exch[1][pr][1][d]) + (double)bias_in[d]);
    }

    // ---- Phase 2a: stage codebook + pre-paired (-0.5||w||^2, 0)
    for (int k = tid; k < Kk; k += NT) {
        float4 c0 = __ldg(reinterpret_cast<const float4*>(cb + k * 8));
        float4 c1 = __ldg(reinterpret_cast<const float4*>(cb + k * 8) + 1);
        reinterpret_cast<float4*>(buf)[k * 2]     = c0;
        reinterpret_cast<float4*>(buf)[k * 2 + 1] = c1;
        double n = (double)c0.x*c0.x + (double)c0.y*c0.y
                 + (double)c0.z*c0.z + (double)c0.w*c0.w
                 + (double)c1.x*c1.x + (double)c1.y*c1.y
                 + (double)c1.z*c1.z + (double)c1.w*c1.w;
        aux2[k] = pk2(-(float)(0.5 * n), 0.0f);
    }
    __syncthreads();

    // ---- Phase 2b: scan this slice's 512 codes in groups of 4, both tokens.
    u64 ep0[4], ep1[4];
    #pragma unroll
    for (int j = 0; j < 4; j++) {
        ep0[j] = pk2(e0[2*j], e0[2*j+1]);
        ep1[j] = pk2(e1[2*j], e1[2*j+1]);
    }
    float b1t0 = -FLT_MAX, b2t0 = -FLT_MAX, b1t1 = -FLT_MAX, b2t1 = -FLT_MAX;
    int   i1t0 = slice*KH, i2t0 = slice*KH, i1t1 = slice*KH, i2t1 = slice*KH;
    const int kbeg = slice * KH;
    #pragma unroll 2
    for (int k = kbeg; k < kbeg + KH; k += 4) {
        const ulonglong2* wp = reinterpret_cast<const ulonglong2*>(buf + k * 8);
        ulonglong2 iab01 = *reinterpret_cast<const ulonglong2*>(&aux2[k]);
        ulonglong2 iab23 = *reinterpret_cast<const ulonglong2*>(&aux2[k + 2]);

        // codes k, k+1
        ulonglong2 wa0 = wp[0], wa1 = wp[1];
        ulonglong2 wb0 = wp[2], wb1 = wp[3];
        u64 da = ffma2(ep0[3], wa1.y, ffma2(ep0[2], wa1.x,
                 ffma2(ep0[1], wa0.y, ffma2(ep0[0], wa0.x, iab01.x))));
        u64 db = ffma2(ep0[3], wb1.y, ffma2(ep0[2], wb1.x,
                 ffma2(ep0[1], wb0.y, ffma2(ep0[0], wb0.x, iab01.y))));
        float lo, hi;
        upk2(da, lo, hi); float sa0 = lo + hi;
        upk2(db, lo, hi); float sb0 = lo + hi;
        da = ffma2(ep1[3], wa1.y, ffma2(ep1[2], wa1.x,
             ffma2(ep1[1], wa0.y, ffma2(ep1[0], wa0.x, iab01.x))));
        db = ffma2(ep1[3], wb1.y, ffma2(ep1[2], wb1.x,
             ffma2(ep1[1], wb0.y, ffma2(ep1[0], wb0.x, iab01.y))));
        upk2(da, lo, hi); float sa1 = lo + hi;
        upk2(db, lo, hi); float sb1 = lo + hi;

        // level-1 reduce (pair 01); ties -> lower k
        bool pa0 = sa0 >= sb0;
        float s01_0 = pa0 ? sa0 : sb0;  int k01_0 = pa0 ? k : k + 1;
        bool pa1 = sa1 >= sb1;
        float s01_1 = pa1 ? sa1 : sb1;  int k01_1 = pa1 ? k : k + 1;

        // codes k+2, k+3 (reuse w registers)
        wa0 = wp[4]; wa1 = wp[5];
        wb0 = wp[6]; wb1 = wp[7];
        da = ffma2(ep0[3], wa1.y, ffma2(ep0[2], wa1.x,
             ffma2(ep0[1], wa0.y, ffma2(ep0[0], wa0.x, iab23.x))));
        db = ffma2(ep0[3], wb1.y, ffma2(ep0[2], wb1.x,
             ffma2(ep0[1], wb0.y, ffma2(ep0[0], wb0.x, iab23.y))));
        upk2(da, lo, hi); float sc0 = lo + hi;
        upk2(db, lo, hi); float sd0 = lo + hi;
        da = ffma2(ep1[3], wa1.y, ffma2(ep1[2], wa1.x,
             ffma2(ep1[1], wa0.y, ffma2(ep1[0], wa0.x, iab23.x))));
        db = ffma2(ep1[3], wb1.y, ffma2(ep1[2], wb1.x,
             ffma2(ep1[1], wb0.y, ffma2(ep1[0], wb0.x, iab23.y))));
        upk2(da, lo, hi); float sc1 = lo + hi;
        upk2(db, lo, hi); float sd1 = lo + hi;

        // level-1 reduce (pair 23)
        bool pb0 = sc0 >= sd0;
        float s23_0 = pb0 ? sc0 : sd0;  int k23_0 = pb0 ? k + 2 : k + 3;
        bool pb1 = sc1 >= sd1;
        float s23_1 = pb1 ? sc1 : sd1;  int k23_1 = pb1 ? k + 2 : k + 3;

        // level-2 reduce; ties -> lower k (01 group has lower indices)
        bool pc0 = s01_0 >= s23_0;
        float sm0 = pc0 ? s01_0 : s23_0;  int km0 = pc0 ? k01_0 : k23_0;
        bool pc1 = s01_1 >= s23_1;
        float sm1 = pc1 ? s01_1 : s23_1;  int km1 = pc1 ? k01_1 : k23_1;

        // branchless top-2 update, once per 4 codes per token
        {
            bool q2 = sm0 > b2t0;
            float c2 = q2 ? sm0 : b2t0;  int j2 = q2 ? km0 : i2t0;
            bool q1 = sm0 > b1t0;
            b2t0 = q1 ? b1t0 : c2;       i2t0 = q1 ? i1t0 : j2;
            b1t0 = q1 ? sm0 : b1t0;      i1t0 = q1 ? km0 : i1t0;
        }
        {
            bool q2 = sm1 > b2t1;
            float c2 = q2 ? sm1 : b2t1;  int j2 = q2 ? km1 : i2t1;
            bool q1 = sm1 > b1t1;
            b2t1 = q1 ? b1t1 : c2;       i2t1 = q1 ? i1t1 : j2;
            b1t1 = q1 ? sm1 : b1t1;      i1t1 = q1 ? km1 : i1t1;
        }
    }
    cand_i[slice][pr][0][0] = i1t0;  cand_i[slice][pr][0][1] = i2t0;
    cand_i[slice][pr][1][0] = i1t1;  cand_i[slice][pr][1][1] = i2t1;
    __syncthreads();

    // ---- fp64 rescore of all 4 candidates per token; lowest index on ties.
    int bi0 = 0, bi1 = 0;
    #pragma unroll
    for (int tk = 0; tk < 2; tk++) {
        const float* ee = tk ? e1 : e0;
        double bscore = -DBL_MAX;
        int    bidx   = Kk;
        #pragma unroll
        for (int j = 0; j < 4; j++) {
            int kc = cand_i[j >> 1][pr][tk][j & 1];
            const float* w = buf + kc * 8;
            double dot = 0.0, nrm = 0.0;
            #pragma unroll
            for (int i = 0; i < Dd; i++) {
                double wi = (double)w[i];
                dot += (double)ee[i] * wi;
                nrm += wi * wi;
            }
            double sc = dot - 0.5 * nrm;
            if (sc > bscore || (sc == bscore && kc < bidx)) {
                bscore = sc; bidx = kc;
            }
        }
        if (tk) bi1 = bidx; else bi0 = bidx;
    }

    // grab winning codes (as d-pairs) before buf is overwritten
    u64 q0p[4], q1p[4];
    {
        const ulonglong2* w0 = reinterpret_cast<const ulonglong2*>(buf + bi0 * 8);
        const ulonglong2* w1 = reinterpret_cast<const ulonglong2*>(buf + bi1 * 8);
        ulonglong2 x0 = w0[0], x1 = w0[1], y0 = w1[0], y1 = w1[1];
        q0p[0] = x0.x; q0p[1] = x0.y; q0p[2] = x1.x; q0p[3] = x1.y;
        q1p[0] = y0.x; q1p[1] = y0.y; q1p[2] = y1.x; q1p[3] = y1.y;
    }
    __syncthreads();   // codebook reads done

    // ---- Phase 3a: stage out_w ([C,D] already c*8+d); aux2 <- (out_b, 0)
    for (int i = tid; i < Cc * Dd; i += NT) buf[i] = out_w[i];
    for (int i = tid; i < Cc; i += NT)      aux2[i] = pk2(out_b[i], 0.0f);
    __syncthreads();

    // ---- Phase 3b: this slice writes channels [cbeg, cbeg+512), 2 tokens.
    float* op = out + (size_t)b * Cc * Tt + t0;
    #pragma unroll 8
    for (int c = cbeg; c < cbeg + CH; c++) {
        const ulonglong2* wp = reinterpret_cast<const ulonglong2*>(buf + c * 8);
        ulonglong2 wA = wp[0], wB = wp[1];
        u64 ic = aux2[c];
        u64 d0 = ffma2(q0p[3], wB.y, ffma2(q0p[2], wB.x,
                 ffma2(q0p[1], wA.y, ffma2(q0p[0], wA.x, ic))));
        u64 d1 = ffma2(q1p[3], wB.y, ffma2(q1p[2], wB.x,
                 ffma2(q1p[1], wA.y, ffma2(q1p[0], wA.x, ic))));
        float lo, hi;
        upk2(d0, lo, hi); float s0 = lo + hi;
        upk2(d1, lo, hi); float s1 = lo + hi;
        *reinterpret_cast<float2*>(op + (size_t)c * Tt) = make_float2(s0, s1);
    }

    if (slice == 0 && ids_out) {
        *reinterpret_cast<float2*>(ids_out + (size_t)b * Tt + t0) =
            make_float2((float)bi0, (float)bi1);
    }
}

extern "C" void kernel_launch(void* const* d_in, const int* in_sizes, int n_in,
                              void* d_out, int out_size) {
    const float* z     = (const float*)d_in[0];
    const float* in_w  = (const float*)d_in[1];
    const float* in_b  = (const float*)d_in[2];
    const float* cb    = (const float*)d_in[3];
    const float* out_w = (const float*)d_in[4];
    const float* out_b = (const float*)d_in[5];

    float* out = (float*)d_out;
    const long long out_elems = (long long)Bb * Cc * Tt;
    float* ids = (out_size > out_elems) ? out + out_elems : nullptr;

    dim3 grid(Bb * (Tt / TT));   // 256 blocks x 256 threads, 2 tokens/thread
    vq_fused<<<grid, NT>>>(z, in_w, in_b, cb, out_w, out_b, out, ids);
}